// round 2
// baseline (speedup 1.0000x reference)
#include <cuda_runtime.h>
#include <cuda_bf16.h>
#include <cstdint>

#define Bd   64
#define Dd   512
#define Td   50
#define Sd   400
#define KTOP 50
#define H3   1536
#define NEGV (-1e6f)

// ---- output layout (concat of reference return tuple, flattened) ----
#define OFF_G     0
#define SZ_G      (Td*Bd*256)          // 819200
#define OFF_H     (OFF_G + SZ_G)       // 819200
#define SZ_H      (2*Bd*Dd)            // 65536
#define OFF_ATTN  (OFF_H + SZ_H)       // 884736
#define SZ_ATTN   (Td*Bd*Sd)           // 1280000
#define OFF_TATTN (OFF_ATTN + SZ_ATTN) // 2164736
#define SZ_TATTN  (Td*Bd*KTOP)         // 160000
#define OFF_MIX   (OFF_TATTN + SZ_TATTN) // 2324736
#define OFF_GATE  (OFF_MIX + Bd*Dd)    // 2357504

// ---- scratch (device globals; no allocation allowed) ----
__device__ float g_pre [Sd*Bd*Dd];     // [(s*B+b)][512]
__device__ float g_tpre[KTOP*Bd*Dd];
__device__ float g_emb [Td*Bd*Dd];
__device__ float g_Wt_ih0[1024*H3];
__device__ float g_Wt_hh0[Dd*H3];
__device__ float g_Wt_ih1[Dd*H3];
__device__ float g_Wt_hh1[Dd*H3];
__device__ float g_Wt_ro [H3*Dd];
__device__ float g_Wt_q  [Dd*Dd];
__device__ float g_Wt_tq [Dd*Dd];
__device__ float g_Wt_pre[Dd*Dd];
__device__ float g_Wt_tpre[Dd*Dd];
__device__ float g_h0[Bd*Dd], g_h1[Bd*Dd], g_mix[Bd*Dd];
__device__ float g_x0[Bd*1024];
__device__ float g_xr[Bd*H3];
__device__ float g_q[Bd*Dd], g_tq[Bd*Dd], g_gate[Bd];
__device__ float g_c[Bd*Dd], g_tc[Bd*Dd];
#define MAXSPLIT 8
__device__ float g_partA[MAXSPLIT*Bd*H3];
__device__ float g_partB[MAXSPLIT*Bd*H3];

__device__ __forceinline__ float tanh_fast(float x){
    float y; asm("tanh.approx.f32 %0, %1;" : "=f"(y) : "f"(x)); return y;
}
__device__ __forceinline__ float sigm(float x){ return 1.f/(1.f+__expf(-x)); }

// ---------------- precompute kernels ----------------

__global__ void k_transpose(const float* __restrict__ src, float* __restrict__ dst, int R, int C){
    int i = blockIdx.x*blockDim.x + threadIdx.x;
    if (i < R*C){ int r = i / C, c = i % C; dst[(size_t)c*R + r] = src[i]; }
}

__global__ void k_embed(const int* __restrict__ tgt, const float* __restrict__ table){
    int i = blockIdx.x;                     // 0 .. T*B-1
    int tok = tgt[i];
    const float* src = table + (size_t)tok*Dd;
    float* dst = g_emb + (size_t)i*Dd;
    for (int d = threadIdx.x; d < Dd; d += blockDim.x) dst[d] = src[d];
}

__global__ void k_init(const float* __restrict__ hidden, const float* __restrict__ mix0){
    int i = blockIdx.x*blockDim.x + threadIdx.x;
    if (i < Bd*Dd){ g_h0[i] = hidden[i]; g_h1[i] = hidden[Bd*Dd + i]; g_mix[i] = mix0[i]; }
}

// pre[m][n] = sum_k X[m][k]*Wt[k][n] + bias[n], M = L*B (rows), 512x512 weight.
// tile: 128(M) x 64(N), BK=16, 256 threads, 8x4 micro-tile.
__global__ void k_pre(const float* __restrict__ X, const float* __restrict__ Wt,
                      const float* __restrict__ bias, float* __restrict__ C){
    const int m0 = blockIdx.x * 128;
    const int n0 = blockIdx.y * 64;
    __shared__ float as[16][132];
    __shared__ float bs[16][68];
    int tid = threadIdx.x;
    int mi0 = (tid >> 4) * 8;
    int ni0 = (tid & 15) * 4;
    float acc[8][4] = {};
    int lr = tid >> 2;            // 0..63
    int lc = (tid & 3) * 4;       // 0,4,8,12
    for (int k0 = 0; k0 < 512; k0 += 16){
        #pragma unroll
        for (int h = 0; h < 2; h++){
            int row = lr + h*64;
            const float* xp = X + (size_t)(m0+row)*512 + k0 + lc;
            #pragma unroll
            for (int j = 0; j < 4; j++) as[lc+j][row] = xp[j];
        }
        {
            int kk = tid >> 4;            // 0..15
            int nn = (tid & 15) * 4;
            const float* wp = Wt + (size_t)(k0+kk)*512 + n0 + nn;
            #pragma unroll
            for (int j = 0; j < 4; j++) bs[kk][nn+j] = wp[j];
        }
        __syncthreads();
        #pragma unroll
        for (int kk = 0; kk < 16; kk++){
            float av[8], bv[4];
            #pragma unroll
            for (int i = 0; i < 8; i++) av[i] = as[kk][mi0+i];
            #pragma unroll
            for (int j = 0; j < 4; j++) bv[j] = bs[kk][ni0+j];
            #pragma unroll
            for (int i = 0; i < 8; i++)
                #pragma unroll
                for (int j = 0; j < 4; j++) acc[i][j] += av[i]*bv[j];
        }
        __syncthreads();
    }
    #pragma unroll
    for (int i = 0; i < 8; i++){
        float* cp = C + (size_t)(m0+mi0+i)*512 + n0 + ni0;
        #pragma unroll
        for (int j = 0; j < 4; j++) cp[j] = acc[i][j] + bias[n0+ni0+j];
    }
}

// ---------------- per-step GEMM (B=64 rows) with K-split partials ----------------
// part[split][b][n] = sum_{k in split} X[b][k] * Wt[k][n]
__global__ void k_gemm64(const float* __restrict__ X, int ldx,
                         const float* __restrict__ Wt, int Ntot,
                         float* __restrict__ part, int kChunk){
    int n0 = blockIdx.x * 64;
    int split = blockIdx.y;
    int k0 = split * kChunk;
    __shared__ float xs[16][68];
    __shared__ float ws[16][68];
    int tid = threadIdx.x;
    int bb0 = (tid >> 4) * 4;
    int nn0 = (tid & 15) * 4;
    float acc[4][4] = {};
    int lb = tid >> 2;           // 0..63
    int lc = (tid & 3) * 4;
    int kw = tid >> 4;           // 0..15
    int nw = (tid & 15) * 4;
    for (int kk0 = 0; kk0 < kChunk; kk0 += 16){
        const float* xp = X + (size_t)lb*ldx + k0 + kk0 + lc;
        #pragma unroll
        for (int j = 0; j < 4; j++) xs[lc+j][lb] = xp[j];
        const float* wp = Wt + (size_t)(k0+kk0+kw)*Ntot + n0 + nw;
        #pragma unroll
        for (int j = 0; j < 4; j++) ws[kw][nw+j] = wp[j];
        __syncthreads();
        #pragma unroll
        for (int kk = 0; kk < 16; kk++){
            float xv[4], wv[4];
            #pragma unroll
            for (int i = 0; i < 4; i++) xv[i] = xs[kk][bb0+i];
            #pragma unroll
            for (int j = 0; j < 4; j++) wv[j] = ws[kk][nn0+j];
            #pragma unroll
            for (int i = 0; i < 4; i++)
                #pragma unroll
                for (int j = 0; j < 4; j++) acc[i][j] += xv[i]*wv[j];
        }
        __syncthreads();
    }
    float* pp = part + (size_t)split*Bd*Ntot;
    #pragma unroll
    for (int i = 0; i < 4; i++){
        float* cp = pp + (size_t)(bb0+i)*Ntot + n0 + nn0;
        #pragma unroll
        for (int j = 0; j < 4; j++) cp[j] = acc[i][j];
    }
}

// ---------------- step kernels ----------------

__global__ void k_buildx0(const float* __restrict__ emb_t){
    int i = blockIdx.x*blockDim.x + threadIdx.x;
    if (i >= Bd*Dd) return;
    int b = i / Dd, d = i % Dd;
    g_x0[(size_t)b*1024 + d]       = emb_t[i];
    g_x0[(size_t)b*1024 + 512 + d] = g_mix[i];
}

__global__ void k_gru_combine(const float* __restrict__ pGI, int nsGI,
                              const float* __restrict__ pGH, int nsGH,
                              const float* __restrict__ b_ih, const float* __restrict__ b_hh,
                              float* __restrict__ h){
    int i = blockIdx.x*blockDim.x + threadIdx.x;
    if (i >= Bd*Dd) return;
    int b = i / Dd, d = i % Dd;
    float gir = b_ih[d], giz = b_ih[Dd+d], gin = b_ih[2*Dd+d];
    for (int s = 0; s < nsGI; s++){
        const float* p = pGI + (size_t)s*Bd*H3 + (size_t)b*H3;
        gir += p[d]; giz += p[Dd+d]; gin += p[2*Dd+d];
    }
    float ghr = b_hh[d], ghz = b_hh[Dd+d], ghn = b_hh[2*Dd+d];
    for (int s = 0; s < nsGH; s++){
        const float* p = pGH + (size_t)s*Bd*H3 + (size_t)b*H3;
        ghr += p[d]; ghz += p[Dd+d]; ghn += p[2*Dd+d];
    }
    float r = sigm(gir + ghr);
    float z = sigm(giz + ghz);
    float n = tanhf(gin + r*ghn);
    float hp = h[i];
    h[i] = (1.f - z)*n + z*hp;
}

__global__ void k_qcombine(const float* __restrict__ pa, const float* __restrict__ pb, int ns){
    int i = blockIdx.x*blockDim.x + threadIdx.x;
    if (i >= Bd*Dd) return;
    float s1 = 0.f, s2 = 0.f;
    for (int s = 0; s < ns; s++){
        s1 += pa[(size_t)s*Bd*Dd + i];
        s2 += pb[(size_t)s*Bd*Dd + i];
    }
    g_q[i] = s1; g_tq[i] = s2;
}

__global__ void k_gate(const float* __restrict__ gW, const float* __restrict__ gb,
                       float* __restrict__ out_gate){
    int b = blockIdx.x, lane = threadIdx.x;
    float p = 0.f;
    for (int d = lane; d < Dd; d += 32) p += g_h1[(size_t)b*Dd + d] * gW[d];
    #pragma unroll
    for (int o = 16; o; o >>= 1) p += __shfl_xor_sync(0xffffffffu, p, o);
    if (lane == 0){
        float g = sigm(p + gb[0]);
        g_gate[b] = g;
        out_gate[b] = g;
    }
}

template<int L>
__global__ void k_attn(const float* __restrict__ pre,   // [(l*B+b)][512]
                       const float* __restrict__ ctx,   // [(l*B+b)][512]
                       const float* __restrict__ mask,  // [B][L]
                       const float* __restrict__ q,     // [B][512]
                       const float* __restrict__ v,     // [512]
                       float* __restrict__ attn_out,    // [b*L + l] (t offset applied)
                       float* __restrict__ c_out){      // [B*512]
    int b = blockIdx.x;
    __shared__ float qv[512], vv[512], e[L], red[64];
    int tid = threadIdx.x;
    for (int d = tid; d < 512; d += 256){ qv[d] = q[(size_t)b*512 + d]; vv[d] = v[d]; }
    __syncthreads();
    int warp = tid >> 5, lane = tid & 31;
    for (int l = warp; l < L; l += 8){
        const float* pp = pre + ((size_t)l*Bd + b)*512;
        float p = 0.f;
        for (int a = lane; a < 512; a += 32) p += vv[a] * tanh_fast(pp[a] + qv[a]);
        #pragma unroll
        for (int o = 16; o; o >>= 1) p += __shfl_xor_sync(0xffffffffu, p, o);
        if (lane == 0){
            if (mask[(size_t)b*L + l] > 0.5f) p = NEGV;
            e[l] = p;
        }
    }
    __syncthreads();
    float m = -1e30f;
    for (int l = tid; l < L; l += 256) m = fmaxf(m, e[l]);
    #pragma unroll
    for (int o = 16; o; o >>= 1) m = fmaxf(m, __shfl_xor_sync(0xffffffffu, m, o));
    if (lane == 0) red[warp] = m;
    __syncthreads();
    if (tid == 0){
        float mm = red[0];
        for (int w = 1; w < 8; w++) mm = fmaxf(mm, red[w]);
        red[32] = mm;
    }
    __syncthreads();
    m = red[32];
    float ssum = 0.f;
    for (int l = tid; l < L; l += 256){ float ex = __expf(e[l] - m); e[l] = ex; ssum += ex; }
    #pragma unroll
    for (int o = 16; o; o >>= 1) ssum += __shfl_xor_sync(0xffffffffu, ssum, o);
    if (lane == 0) red[warp] = ssum;
    __syncthreads();
    if (tid == 0){
        float t = 0.f;
        for (int w = 0; w < 8; w++) t += red[w];
        red[33] = 1.f / t;
    }
    __syncthreads();
    float inv = red[33];
    for (int l = tid; l < L; l += 256){
        float a = e[l] * inv; e[l] = a;
        attn_out[(size_t)b*L + l] = a;
    }
    __syncthreads();
    for (int d = tid; d < 512; d += 256){
        float a0 = 0.f, a1 = 0.f, a2 = 0.f, a3 = 0.f;
        int l = 0;
        for (; l + 3 < L; l += 4){
            a0 += e[l]   * ctx[((size_t)(l  )*Bd + b)*512 + d];
            a1 += e[l+1] * ctx[((size_t)(l+1)*Bd + b)*512 + d];
            a2 += e[l+2] * ctx[((size_t)(l+2)*Bd + b)*512 + d];
            a3 += e[l+3] * ctx[((size_t)(l+3)*Bd + b)*512 + d];
        }
        for (; l < L; l++) a0 += e[l] * ctx[((size_t)l*Bd + b)*512 + d];
        c_out[(size_t)b*512 + d] = a0 + a1 + a2 + a3;
    }
}

__global__ void k_mix(const float* __restrict__ emb_t, float* __restrict__ out_mix, int isLast){
    int i = blockIdx.x*blockDim.x + threadIdx.x;
    if (i >= Bd*Dd) return;
    int b = i / Dd, d = i % Dd;
    float g = g_gate[b];
    float mval = g * g_c[i] + (1.f - g) * g_tc[i];
    g_mix[i] = mval;
    g_xr[(size_t)b*H3 + d]        = emb_t[i];
    g_xr[(size_t)b*H3 + 512 + d]  = g_h1[i];
    g_xr[(size_t)b*H3 + 1024 + d] = mval;
    if (isLast) out_mix[i] = mval;
}

__global__ void k_ro(const float* __restrict__ part, int ns,
                     const float* __restrict__ rb, float* __restrict__ outg){
    int i = blockIdx.x*blockDim.x + threadIdx.x;
    if (i >= Bd*256) return;
    int b = i / 256, j = i % 256;
    float r0 = rb[2*j], r1 = rb[2*j+1];
    for (int s = 0; s < ns; s++){
        const float* p = part + (size_t)s*Bd*512 + (size_t)b*512;
        r0 += p[2*j]; r1 += p[2*j+1];
    }
    outg[(size_t)b*256 + j] = fmaxf(r0, r1);
}

__global__ void k_copy(const float* __restrict__ s, float* __restrict__ d, int n){
    int i = blockIdx.x*blockDim.x + threadIdx.x;
    if (i < n) d[i] = s[i];
}

// ---------------- host ----------------

static float* sym(const void* symbol){
    void* p = nullptr;
    cudaGetSymbolAddress(&p, symbol);
    return (float*)p;
}

extern "C" void kernel_launch(void* const* d_in, const int* in_sizes, int n_in,
                              void* d_out, int out_size){
    const int*   tgt        = (const int*)  d_in[0];
    const float* hidden     = (const float*)d_in[1];
    const float* context    = (const float*)d_in[2];
    const float* smask      = (const float*)d_in[3];
    const float* tcontext   = (const float*)d_in[4];
    const float* tmask      = (const float*)d_in[5];
    const float* mix0       = (const float*)d_in[6];
    const float* emb_table  = (const float*)d_in[7];
    const float* W_ih0      = (const float*)d_in[8];
    const float* W_hh0      = (const float*)d_in[9];
    const float* b_ih0      = (const float*)d_in[10];
    const float* b_hh0      = (const float*)d_in[11];
    const float* W_ih1      = (const float*)d_in[12];
    const float* W_hh1      = (const float*)d_in[13];
    const float* b_ih1      = (const float*)d_in[14];
    const float* b_hh1      = (const float*)d_in[15];
    const float* attn_pre_W = (const float*)d_in[16];
    const float* attn_pre_b = (const float*)d_in[17];
    const float* attn_q_W   = (const float*)d_in[18];
    const float* attn_v     = (const float*)d_in[19];
    const float* tattn_pre_W= (const float*)d_in[20];
    const float* tattn_pre_b= (const float*)d_in[21];
    const float* tattn_q_W  = (const float*)d_in[22];
    const float* tattn_v    = (const float*)d_in[23];
    const float* readout_W  = (const float*)d_in[24];
    const float* readout_b  = (const float*)d_in[25];
    const float* gate_W     = (const float*)d_in[26];
    const float* gate_b     = (const float*)d_in[27];
    float* out = (float*)d_out;

    float* pWt_ih0 = sym(g_Wt_ih0); float* pWt_hh0 = sym(g_Wt_hh0);
    float* pWt_ih1 = sym(g_Wt_ih1); float* pWt_hh1 = sym(g_Wt_hh1);
    float* pWt_ro  = sym(g_Wt_ro);  float* pWt_q   = sym(g_Wt_q);
    float* pWt_tq  = sym(g_Wt_tq);  float* pWt_pre = sym(g_Wt_pre);
    float* pWt_tpre= sym(g_Wt_tpre);
    float* pPre = sym(g_pre);  float* pTpre = sym(g_tpre);
    float* pEmb = sym(g_emb);
    float* pH0 = sym(g_h0); float* pH1 = sym(g_h1);
    float* pX0 = sym(g_x0); float* pXr = sym(g_xr);
    float* pQ = sym(g_q);   float* pTq = sym(g_tq);
    float* pC = sym(g_c);   float* pTc = sym(g_tc);
    float* pPA = sym(g_partA); float* pPB = sym(g_partB);

    const int TPB = 256;
    auto nb = [](int n){ return (n + 255) / 256; };

    // ---- precompute ----
    k_transpose<<<nb(1536*1024), TPB>>>(W_ih0, pWt_ih0, 1536, 1024);
    k_transpose<<<nb(1536*512),  TPB>>>(W_hh0, pWt_hh0, 1536, 512);
    k_transpose<<<nb(1536*512),  TPB>>>(W_ih1, pWt_ih1, 1536, 512);
    k_transpose<<<nb(1536*512),  TPB>>>(W_hh1, pWt_hh1, 1536, 512);
    k_transpose<<<nb(512*1536),  TPB>>>(readout_W, pWt_ro, 512, 1536);
    k_transpose<<<nb(512*512),   TPB>>>(attn_q_W,  pWt_q,  512, 512);
    k_transpose<<<nb(512*512),   TPB>>>(tattn_q_W, pWt_tq, 512, 512);
    k_transpose<<<nb(512*512),   TPB>>>(attn_pre_W,  pWt_pre,  512, 512);
    k_transpose<<<nb(512*512),   TPB>>>(tattn_pre_W, pWt_tpre, 512, 512);
    k_embed<<<Td*Bd, TPB>>>(tgt, emb_table);
    k_init<<<nb(Bd*Dd), TPB>>>(hidden, mix0);
    k_pre<<<dim3((Sd*Bd)/128, 8),   TPB>>>(context,  pWt_pre,  attn_pre_b,  pPre);
    k_pre<<<dim3((KTOP*Bd)/128, 8), TPB>>>(tcontext, pWt_tpre, tattn_pre_b, pTpre);

    // ---- sequential steps ----
    for (int t = 0; t < Td; t++){
        const float* emb_t = pEmb + (size_t)t*Bd*Dd;

        k_buildx0<<<nb(Bd*Dd), TPB>>>(emb_t);
        // GRU layer 0
        k_gemm64<<<dim3(24, 8), TPB>>>(pX0, 1024, pWt_ih0, H3, pPA, 128);
        k_gemm64<<<dim3(24, 4), TPB>>>(pH0, 512,  pWt_hh0, H3, pPB, 128);
        k_gru_combine<<<nb(Bd*Dd), TPB>>>(pPA, 8, pPB, 4, b_ih0, b_hh0, pH0);
        // GRU layer 1
        k_gemm64<<<dim3(24, 4), TPB>>>(pH0, 512, pWt_ih1, H3, pPA, 128);
        k_gemm64<<<dim3(24, 4), TPB>>>(pH1, 512, pWt_hh1, H3, pPB, 128);
        k_gru_combine<<<nb(Bd*Dd), TPB>>>(pPA, 4, pPB, 4, b_ih1, b_hh1, pH1);
        // queries + gate
        k_gemm64<<<dim3(8, 4), TPB>>>(pH1, 512, pWt_q,  512, pPA, 128);
        k_gemm64<<<dim3(8, 4), TPB>>>(pH1, 512, pWt_tq, 512, pPB, 128);
        k_qcombine<<<nb(Bd*Dd), TPB>>>(pPA, pPB, 4);
        k_gate<<<Bd, 32>>>(gate_W, gate_b, out + OFF_GATE + (size_t)t*Bd);
        // attentions
        k_attn<Sd><<<Bd, TPB>>>(pPre, context, smask, pQ, attn_v,
                                out + OFF_ATTN + (size_t)t*Bd*Sd, pC);
        k_attn<KTOP><<<Bd, TPB>>>(pTpre, tcontext, tmask, pTq, tattn_v,
                                  out + OFF_TATTN + (size_t)t*Bd*KTOP, pTc);
        // mix + readout
        k_mix<<<nb(Bd*Dd), TPB>>>(emb_t, out + OFF_MIX, (t == Td-1) ? 1 : 0);
        k_gemm64<<<dim3(8, 8), TPB>>>(pXr, H3, pWt_ro, 512, pPA, 192);
        k_ro<<<nb(Bd*256), TPB>>>(pPA, 8, readout_b, out + OFF_G + (size_t)t*Bd*256);
    }

    // ---- finals ----
    k_copy<<<nb(Bd*Dd), TPB>>>(pH0, out + OFF_H, Bd*Dd);
    k_copy<<<nb(Bd*Dd), TPB>>>(pH1, out + OFF_H + Bd*Dd, Bd*Dd);
}